// round 9
// baseline (speedup 1.0000x reference)
#include <cuda_runtime.h>
#include <cuda_bf16.h>
#include <cstdint>

#define N_NODES 100000
#define N_EDGES 1600000
#define D 128
#define D_OUT 16

#define SCAN_B 1024
#define NCHUNK ((N_NODES + SCAN_B - 1) / SCAN_B)   // 98

// ---------------- device scratch (static: no allocation allowed) ----------------
__device__ int   g_deg[N_NODES];
__device__ int   g_csr_ptr[N_NODES + 1];
__device__ int   g_cursor[N_NODES];
__device__ int   g_csr_src[N_EDGES];
__device__ volatile int g_bsum[NCHUNK];
__device__ volatile int g_done1;
__device__ volatile int g_done2;
__device__ float g_deg_inv[N_NODES];
__device__ float g_mean[(size_t)N_NODES * D];
__device__ float g_bufA[(size_t)N_NODES * D];
__device__ float g_bufB[(size_t)N_NODES * D];
// pre-split transposed weights: [6 matrices][n=128][k=128] bf16 hi/lo
__device__ __nv_bfloat16 g_wh[6 * 128 * 128];
__device__ __nv_bfloat16 g_wl[6 * 128 * 128];

// ---------------- helpers ----------------
__device__ __forceinline__ uint32_t smem_u32(const void* p) {
    uint32_t a;
    asm("{ .reg .u64 t; cvta.to.shared.u64 t, %1; cvt.u32.u64 %0, t; }" : "=r"(a) : "l"(p));
    return a;
}
__device__ __forceinline__ void ldm_x4(uint32_t& r0, uint32_t& r1, uint32_t& r2,
                                       uint32_t& r3, uint32_t addr) {
    asm volatile("ldmatrix.sync.aligned.m8n8.x4.shared.b16 {%0,%1,%2,%3}, [%4];"
                 : "=r"(r0), "=r"(r1), "=r"(r2), "=r"(r3) : "r"(addr));
}
__device__ __forceinline__ void mma_bf16(float* c, const uint32_t* a, const uint32_t* b) {
    asm volatile(
        "mma.sync.aligned.m16n8k16.row.col.f32.bf16.bf16.f32 "
        "{%0,%1,%2,%3}, {%4,%5,%6,%7}, {%8,%9}, {%0,%1,%2,%3};"
        : "+f"(c[0]), "+f"(c[1]), "+f"(c[2]), "+f"(c[3])
        : "r"(a[0]), "r"(a[1]), "r"(a[2]), "r"(a[3]), "r"(b[0]), "r"(b[1]));
}

// ---------------- prep: wsplit x6 + zero_deg + sentinels (one kernel) ----------------
#define PREP_WS_B   384     // 6*16384 / 256
#define PREP_ZD_B   391     // 100000 / 256
#define PREP_GRID   (PREP_WS_B + PREP_ZD_B)

__global__ void k_prep(const float* __restrict__ Wn0, const float* __restrict__ Ws0,
                       const float* __restrict__ Wn1, const float* __restrict__ Ws1,
                       const float* __restrict__ Wn2, const float* __restrict__ Ws2,
                       __nv_bfloat16* __restrict__ wh, __nv_bfloat16* __restrict__ wl) {
    int b = blockIdx.x;
    int t = threadIdx.x;
    if (b < PREP_WS_B) {
        int idx = b * 256 + t;            // [0, 98304)
        int mat = idx >> 14;
        int within = idx & 16383;
        int n = within & 127;
        int k = within >> 7;
        const float* W;
        switch (mat) {
            case 0: W = Wn0; break;
            case 1: W = Ws0; break;
            case 2: W = Wn1; break;
            case 3: W = Ws1; break;
            case 4: W = Wn2; break;
            default: W = Ws2; break;
        }
        float v = W[k * 128 + n];
        __nv_bfloat16 h = __float2bfloat16(v);
        __nv_bfloat16 l = __float2bfloat16(v - __bfloat162float(h));
        wh[mat * 16384 + n * 128 + k] = h;
        wl[mat * 16384 + n * 128 + k] = l;
    } else {
        int zb = b - PREP_WS_B;
        int i = zb * 256 + t;
        if (i < N_NODES) g_deg[i] = 0;
        if (zb == 0) {
            if (t < NCHUNK) g_bsum[t] = -1;
            if (t == NCHUNK)     g_done1 = 0;
            if (t == NCHUNK + 1) g_done2 = 0;
        }
    }
}

// ---------------- fused hist + scan + fill (NCHUNK x 1024 co-resident) ----------------
__global__ void __launch_bounds__(SCAN_B)
k_scanfill(const int* __restrict__ src, const int* __restrict__ dst) {
    __shared__ int s[SCAN_B];
    __shared__ int agg_sh[NCHUNK];
    __shared__ int s_off;
    const int bid = blockIdx.x;
    const int tid = threadIdx.x;
    const int gi = bid * SCAN_B + tid;

    // ---- phase 0: histogram (grid-stride, independent atomics) ----
    for (int e = bid * SCAN_B + tid; e < N_EDGES; e += NCHUNK * SCAN_B) {
        atomicAdd(&g_deg[dst[e]], 1);
    }
    __threadfence();
    __syncthreads();
    if (tid == 0) {
        atomicAdd((int*)&g_done1, 1);
        while (g_done1 < NCHUNK) { }
    }
    __syncthreads();

    // ---- phase 1: scan ----
    int v = (gi < N_NODES) ? g_deg[gi] : 0;
    s[tid] = v;
    __syncthreads();
#pragma unroll
    for (int off = 1; off < SCAN_B; off <<= 1) {
        int t = (tid >= off) ? s[tid - off] : 0;
        __syncthreads();
        s[tid] += t;
        __syncthreads();
    }
    int inclusive = s[tid];
    int local_ex = inclusive - v;

    if (tid == SCAN_B - 1) {
        __threadfence();
        g_bsum[bid] = inclusive;   // publish chunk aggregate
    }
    if (tid < NCHUNK) {
        int val = 0;
        if (tid < bid) {
            do { val = g_bsum[tid]; } while (val < 0);
        }
        agg_sh[tid] = (tid < bid) ? val : 0;
    }
    __syncthreads();
    if (tid == 0) {
        int run = 0;
#pragma unroll 1
        for (int i = 0; i < NCHUNK; i++) run += agg_sh[i];
        s_off = run;
    }
    __syncthreads();
    int offset = s_off;

    if (gi < N_NODES) {
        int p = local_ex + offset;
        g_csr_ptr[gi] = p;
        g_cursor[gi]  = p;
        g_deg_inv[gi] = 1.0f / (float)max(v, 1);
    }
    if (gi == 0) g_csr_ptr[N_NODES] = N_EDGES;

    // ---- barrier: all cursors visible before fill ----
    __threadfence();
    __syncthreads();
    if (tid == 0) {
        atomicAdd((int*)&g_done2, 1);
        while (g_done2 < NCHUNK) { }
    }
    __syncthreads();

    // ---- phase 2: fill ----
    for (int e = bid * SCAN_B + tid; e < N_EDGES; e += NCHUNK * SCAN_B) {
        int pos = atomicAdd(&g_cursor[dst[e]], 1);
        g_csr_src[pos] = src[e];
    }
}

// ---------------- fp32 mean aggregation: one warp per node, 4-deep batches ----------------
__global__ void k_aggregate(const float* __restrict__ in, float* __restrict__ out) {
    int warp = (blockIdx.x * blockDim.x + threadIdx.x) >> 5;
    int lane = threadIdx.x & 31;
    if (warp >= N_NODES) return;
    int beg = g_csr_ptr[warp];
    int end = g_csr_ptr[warp + 1];

    float4 acc[4];
#pragma unroll
    for (int u = 0; u < 4; ++u) acc[u] = make_float4(0.f, 0.f, 0.f, 0.f);

    int e = beg;
#pragma unroll 1
    for (; e + 4 <= end; e += 4) {
        int s[4];
#pragma unroll
        for (int u = 0; u < 4; ++u) s[u] = g_csr_src[e + u];
        float4 r[4];
#pragma unroll
        for (int u = 0; u < 4; ++u)
            r[u] = __ldg(((const float4*)(in + (size_t)s[u] * D)) + lane);
#pragma unroll
        for (int u = 0; u < 4; ++u) {
            acc[u].x += r[u].x; acc[u].y += r[u].y;
            acc[u].z += r[u].z; acc[u].w += r[u].w;
        }
    }
#pragma unroll 1
    for (; e < end; ++e) {
        int s = g_csr_src[e];
        float4 r = __ldg(((const float4*)(in + (size_t)s * D)) + lane);
        acc[0].x += r.x; acc[0].y += r.y; acc[0].z += r.z; acc[0].w += r.w;
    }
    float4 o;
    o.x = acc[0].x + acc[1].x + acc[2].x + acc[3].x;
    o.y = acc[0].y + acc[1].y + acc[2].y + acc[3].y;
    o.z = acc[0].z + acc[1].z + acc[2].z + acc[3].z;
    o.w = acc[0].w + acc[1].w + acc[2].w + acc[3].w;
    float di = g_deg_inv[warp];
    o.x *= di; o.y *= di; o.z *= di; o.w *= di;
    ((float4*)(out + (size_t)warp * D))[lane] = o;
}

// ---------------- mma.sync fused SAGE GEMM ----------------
#define TSTRIDE 144
#define TILE_BYTES (128 * TSTRIDE)
#define SM_BIAS  256
#define SM_AHI   1024
#define SM_ALO   (SM_AHI + TILE_BYTES)
#define SM_BHI   (SM_ALO + TILE_BYTES)
#define SM_BLO   (SM_BHI + TILE_BYTES)
#define SM_NEED  (SM_BLO + TILE_BYTES + 1024)

__global__ void __launch_bounds__(256)
k_sage_mma(const float* __restrict__ Xs, const float* __restrict__ Mn,
           const __nv_bfloat16* __restrict__ wh, const __nv_bfloat16* __restrict__ wl,
           const float* __restrict__ bias, float* __restrict__ out, int relu) {
    extern __shared__ __align__(16) char smraw[];
    uint32_t raw = smem_u32(smraw);
    uint32_t sbase = (raw + 1023u) & ~1023u;
    char* smem = smraw + (sbase - raw);

    const int tid = threadIdx.x;
    const int wid = tid >> 5;
    const int lid = tid & 31;
    const int block_row = blockIdx.x * 128;
    const int mrow = (wid & 3) * 32;
    const int ncol = (wid >> 2) * 64;

    float* sbias = (float*)(smem + SM_BIAS);
    if (tid < 128) sbias[tid] = bias[tid];

    float acc[2][8][4];
#pragma unroll
    for (int mb = 0; mb < 2; ++mb)
#pragma unroll
        for (int nb = 0; nb < 8; ++nb)
#pragma unroll
            for (int r = 0; r < 4; ++r) acc[mb][nb][r] = 0.f;

    const uint32_t a_lane_off = (uint32_t)(((lid & 7) + ((lid >> 3) & 1) * 8) * TSTRIDE
                                           + ((lid >> 4) * 8) * 2);
    const uint32_t b_lane_off = (uint32_t)((((lid >> 4) * 8) + (lid & 7)) * TSTRIDE
                                           + (((lid >> 3) & 1) * 8) * 2);

#pragma unroll 1
    for (int c = 0; c < 4; ++c) {
        const int phase = c >> 1;
        const int kc = c & 1;
        const float* __restrict__ A = phase ? Xs : Mn;
        const __nv_bfloat16* __restrict__ bhsrc = wh + phase * 16384 + kc * 64;
        const __nv_bfloat16* __restrict__ blsrc = wl + phase * 16384 + kc * 64;

        __syncthreads();

#pragma unroll
        for (int it = 0; it < 4; ++it) {
            int g = tid + it * 256;
            int row = g >> 3, seg = g & 7;
            int grow = block_row + row;
            float4 v0 = make_float4(0.f, 0.f, 0.f, 0.f), v1 = v0;
            if (grow < N_NODES) {
                const float4* p = (const float4*)(A + (size_t)grow * D + kc * 64 + seg * 8);
                v0 = p[0]; v1 = p[1];
            }
            float f[8] = {v0.x, v0.y, v0.z, v0.w, v1.x, v1.y, v1.z, v1.w};
            uint32_t hv[4], lv[4];
#pragma unroll
            for (int eI = 0; eI < 4; ++eI) {
                float a0 = f[2 * eI], a1 = f[2 * eI + 1];
                __nv_bfloat16 h0 = __float2bfloat16(a0);
                __nv_bfloat16 h1 = __float2bfloat16(a1);
                __nv_bfloat16 l0 = __float2bfloat16(a0 - __bfloat162float(h0));
                __nv_bfloat16 l1 = __float2bfloat16(a1 - __bfloat162float(h1));
                hv[eI] = (uint32_t)__bfloat16_as_ushort(h0) |
                         ((uint32_t)__bfloat16_as_ushort(h1) << 16);
                lv[eI] = (uint32_t)__bfloat16_as_ushort(l0) |
                         ((uint32_t)__bfloat16_as_ushort(l1) << 16);
            }
            uint32_t off = (uint32_t)(row * TSTRIDE + seg * 16);
            *(uint4*)(smem + SM_AHI + off) = make_uint4(hv[0], hv[1], hv[2], hv[3]);
            *(uint4*)(smem + SM_ALO + off) = make_uint4(lv[0], lv[1], lv[2], lv[3]);
        }
#pragma unroll
        for (int it = 0; it < 4; ++it) {
            int g = tid + it * 256;
            int n = g >> 3, seg = g & 7;
            uint32_t off = (uint32_t)(n * TSTRIDE + seg * 16);
            *(uint4*)(smem + SM_BHI + off) = *(const uint4*)(bhsrc + n * 128 + seg * 8);
            *(uint4*)(smem + SM_BLO + off) = *(const uint4*)(blsrc + n * 128 + seg * 8);
        }
        __syncthreads();

        const uint32_t ahi_base = sbase + SM_AHI + (uint32_t)(mrow * TSTRIDE) + a_lane_off;
        const uint32_t alo_base = sbase + SM_ALO + (uint32_t)(mrow * TSTRIDE) + a_lane_off;
        const uint32_t bhi_base = sbase + SM_BHI + (uint32_t)(ncol * TSTRIDE) + b_lane_off;
        const uint32_t blo_base = sbase + SM_BLO + (uint32_t)(ncol * TSTRIDE) + b_lane_off;

#pragma unroll
        for (int k16 = 0; k16 < 4; ++k16) {
            const uint32_t kb = (uint32_t)(k16 * 32);
            uint32_t ah[2][4], al[2][4];
#pragma unroll
            for (int mb = 0; mb < 2; ++mb) {
                uint32_t mo = (uint32_t)(mb * 16 * TSTRIDE) + kb;
                ldm_x4(ah[mb][0], ah[mb][1], ah[mb][2], ah[mb][3], ahi_base + mo);
                ldm_x4(al[mb][0], al[mb][1], al[mb][2], al[mb][3], alo_base + mo);
            }
#pragma unroll
            for (int jp = 0; jp < 4; ++jp) {
                uint32_t no = (uint32_t)(jp * 16 * TSTRIDE) + kb;
                uint32_t bh[4], bl[4];
                ldm_x4(bh[0], bh[1], bh[2], bh[3], bhi_base + no);
                ldm_x4(bl[0], bl[1], bl[2], bl[3], blo_base + no);
#pragma unroll
                for (int mb = 0; mb < 2; ++mb) {
                    mma_bf16(acc[mb][jp * 2 + 0], ah[mb], bh + 0);
                    mma_bf16(acc[mb][jp * 2 + 1], ah[mb], bh + 2);
                    mma_bf16(acc[mb][jp * 2 + 0], ah[mb], bl + 0);
                    mma_bf16(acc[mb][jp * 2 + 1], ah[mb], bl + 2);
                    mma_bf16(acc[mb][jp * 2 + 0], al[mb], bh + 0);
                    mma_bf16(acc[mb][jp * 2 + 1], al[mb], bh + 2);
                }
            }
        }
    }

    // ---- epilogue ----
    const int r4 = lid >> 2;
    const int c2 = (lid & 3) * 2;
#pragma unroll
    for (int mb = 0; mb < 2; ++mb) {
#pragma unroll
        for (int nb = 0; nb < 8; ++nb) {
            int col = ncol + nb * 8 + c2;
            float b0 = sbias[col], b1 = sbias[col + 1];
            int row0 = block_row + mrow + mb * 16 + r4;
            int row1 = row0 + 8;
            float2 o0, o1;
            o0.x = acc[mb][nb][0] + b0; o0.y = acc[mb][nb][1] + b1;
            o1.x = acc[mb][nb][2] + b0; o1.y = acc[mb][nb][3] + b1;
            if (relu) {
                o0.x = fmaxf(o0.x, 0.f); o0.y = fmaxf(o0.y, 0.f);
                o1.x = fmaxf(o1.x, 0.f); o1.y = fmaxf(o1.y, 0.f);
            }
            if (row0 < N_NODES) *(float2*)(out + (size_t)row0 * D + col) = o0;
            if (row1 < N_NODES) *(float2*)(out + (size_t)row1 * D + col) = o1;
        }
    }
}

// ---------------- final fc (128->16) + log_softmax, one warp per node ----------------
__global__ void k_fc_logsoftmax(const float* __restrict__ emb,
                                const float* __restrict__ Wfc,
                                const float* __restrict__ bfc,
                                float* __restrict__ outp) {
    __shared__ float sWt[D_OUT * D];
    __shared__ float sb[D_OUT];
    for (int i = threadIdx.x; i < D * D_OUT; i += blockDim.x) {
        int k = i >> 4, j = i & 15;
        sWt[j * D + k] = Wfc[i];
    }
    if (threadIdx.x < D_OUT) sb[threadIdx.x] = bfc[threadIdx.x];
    __syncthreads();

    int warp = (blockIdx.x * blockDim.x + threadIdx.x) >> 5;
    int lane = threadIdx.x & 31;
    if (warp >= N_NODES) return;

    float4 e4 = ((const float4*)(emb + (size_t)warp * D))[lane];
    float y[D_OUT];
#pragma unroll
    for (int j = 0; j < D_OUT; j++) {
        float4 w = ((const float4*)(sWt + j * D))[lane];
        y[j] = e4.x * w.x + e4.y * w.y + e4.z * w.z + e4.w * w.w;
    }
#pragma unroll
    for (int off = 16; off >= 1; off >>= 1)
#pragma unroll
        for (int j = 0; j < D_OUT; j++)
            y[j] += __shfl_xor_sync(0xFFFFFFFFu, y[j], off);

    float m = -1e30f;
#pragma unroll
    for (int j = 0; j < D_OUT; j++) { y[j] += sb[j]; m = fmaxf(m, y[j]); }
    float ssum = 0.f;
#pragma unroll
    for (int j = 0; j < D_OUT; j++) ssum += __expf(y[j] - m);
    float lse = __logf(ssum) + m;
    if (lane < D_OUT) outp[(size_t)warp * D_OUT + lane] = y[lane] - lse;
}

// ---------------- launcher ----------------
extern "C" void kernel_launch(void* const* d_in, const int* in_sizes, int n_in,
                              void* d_out, int out_size) {
    const float* x   = (const float*)d_in[0];
    const int*   ei  = (const int*)d_in[1];
    const float* Wn0 = (const float*)d_in[2];
    const float* Ws0 = (const float*)d_in[3];
    const float* b0  = (const float*)d_in[4];
    const float* Wn1 = (const float*)d_in[5];
    const float* Ws1 = (const float*)d_in[6];
    const float* b1  = (const float*)d_in[7];
    const float* Wn2 = (const float*)d_in[8];
    const float* Ws2 = (const float*)d_in[9];
    const float* b2  = (const float*)d_in[10];
    const float* Wfc = (const float*)d_in[11];
    const float* bfc = (const float*)d_in[12];

    float* out  = (float*)d_out;
    float* emb  = out;                               // [N, 128]
    float* logp = out + (size_t)N_NODES * D;         // [N, 16]

    const int* src = ei;
    const int* dst = ei + N_EDGES;

    void *p_mean, *p_A, *p_B, *p_wh, *p_wl;
    cudaGetSymbolAddress(&p_mean, g_mean);
    cudaGetSymbolAddress(&p_A, g_bufA);
    cudaGetSymbolAddress(&p_B, g_bufB);
    cudaGetSymbolAddress(&p_wh, g_wh);
    cudaGetSymbolAddress(&p_wl, g_wl);
    float* mean = (float*)p_mean;
    float* A = (float*)p_A;
    float* B = (float*)p_B;
    __nv_bfloat16* wh = (__nv_bfloat16*)p_wh;
    __nv_bfloat16* wl = (__nv_bfloat16*)p_wl;

    static int smem_set = 0;
    if (!smem_set) {
        cudaFuncSetAttribute(k_sage_mma, cudaFuncAttributeMaxDynamicSharedMemorySize, SM_NEED);
        smem_set = 1;
    }

    const int GEMM_B = (N_NODES + 127) / 128;      // 782
    const int WARP_B = (N_NODES * 32 + 255) / 256; // 12500

    // 1: prep (wsplit x6, zero deg, sentinels)
    k_prep<<<PREP_GRID, 256>>>(Wn0, Ws0, Wn1, Ws1, Wn2, Ws2, wh, wl);
    // 2: fused hist + scan + fill
    k_scanfill<<<NCHUNK, SCAN_B>>>(src, dst);

    // 3: layer-0 aggregate
    k_aggregate<<<WARP_B, 256>>>(x, mean);
    // 4: layer-0 gemm  <-- profiled launch
    k_sage_mma<<<GEMM_B, 256, SM_NEED>>>(x, mean, wh + 0 * 16384, wl + 0 * 16384, b0, A, 1);
    // layer 1
    k_aggregate<<<WARP_B, 256>>>(A, mean);
    k_sage_mma<<<GEMM_B, 256, SM_NEED>>>(A, mean, wh + 2 * 16384, wl + 2 * 16384, b1, B, 1);
    // layer 2 -> emb into d_out
    k_aggregate<<<WARP_B, 256>>>(B, mean);
    k_sage_mma<<<GEMM_B, 256, SM_NEED>>>(B, mean, wh + 4 * 16384, wl + 4 * 16384, b2, emb, 0);
    // fc + log_softmax
    k_fc_logsoftmax<<<WARP_B, 256>>>(emb, Wfc, bfc, logp);
}

// round 10
// speedup vs baseline: 1.1799x; 1.1799x over previous
#include <cuda_runtime.h>
#include <cuda_bf16.h>
#include <cstdint>

#define N_NODES 100000
#define N_EDGES 1600000
#define D 128
#define D_OUT 16

#define SCAN_B 1024
#define NCHUNK ((N_NODES + SCAN_B - 1) / SCAN_B)   // 98

// ---------------- device scratch (static: no allocation allowed) ----------------
__device__ int   g_deg[N_NODES];
__device__ int   g_csr_ptr[N_NODES + 1];
__device__ int   g_cursor[N_NODES];
__device__ int   g_csr_src[N_EDGES];
__device__ volatile int g_bsum[NCHUNK];
__device__ volatile int g_done1;
__device__ volatile int g_done2;
__device__ float g_deg_inv[N_NODES];
__device__ float g_mean[(size_t)N_NODES * D];
__device__ float g_bufA[(size_t)N_NODES * D];
__device__ float g_bufB[(size_t)N_NODES * D];
// pre-split transposed weights: [6 matrices][n=128][k=128] bf16 hi/lo
__device__ __nv_bfloat16 g_wh[6 * 128 * 128];
__device__ __nv_bfloat16 g_wl[6 * 128 * 128];

// ---------------- helpers ----------------
__device__ __forceinline__ uint32_t smem_u32(const void* p) {
    uint32_t a;
    asm("{ .reg .u64 t; cvta.to.shared.u64 t, %1; cvt.u32.u64 %0, t; }" : "=r"(a) : "l"(p));
    return a;
}
__device__ __forceinline__ void ldm_x4(uint32_t& r0, uint32_t& r1, uint32_t& r2,
                                       uint32_t& r3, uint32_t addr) {
    asm volatile("ldmatrix.sync.aligned.m8n8.x4.shared.b16 {%0,%1,%2,%3}, [%4];"
                 : "=r"(r0), "=r"(r1), "=r"(r2), "=r"(r3) : "r"(addr));
}
__device__ __forceinline__ void mma_bf16(float* c, const uint32_t* a, const uint32_t* b) {
    asm volatile(
        "mma.sync.aligned.m16n8k16.row.col.f32.bf16.bf16.f32 "
        "{%0,%1,%2,%3}, {%4,%5,%6,%7}, {%8,%9}, {%0,%1,%2,%3};"
        : "+f"(c[0]), "+f"(c[1]), "+f"(c[2]), "+f"(c[3])
        : "r"(a[0]), "r"(a[1]), "r"(a[2]), "r"(a[3]), "r"(b[0]), "r"(b[1]));
}

// ---------------- prep: wsplit x6 + zero_deg + sentinels (one kernel) ----------------
#define PREP_WS_B   384     // 6*16384 / 256
#define PREP_ZD_B   391     // 100000 / 256
#define PREP_GRID   (PREP_WS_B + PREP_ZD_B)

__global__ void k_prep(const float* __restrict__ Wn0, const float* __restrict__ Ws0,
                       const float* __restrict__ Wn1, const float* __restrict__ Ws1,
                       const float* __restrict__ Wn2, const float* __restrict__ Ws2,
                       __nv_bfloat16* __restrict__ wh, __nv_bfloat16* __restrict__ wl) {
    int b = blockIdx.x;
    int t = threadIdx.x;
    if (b < PREP_WS_B) {
        int idx = b * 256 + t;            // [0, 98304)
        int mat = idx >> 14;
        int within = idx & 16383;
        int n = within & 127;
        int k = within >> 7;
        const float* W;
        switch (mat) {
            case 0: W = Wn0; break;
            case 1: W = Ws0; break;
            case 2: W = Wn1; break;
            case 3: W = Ws1; break;
            case 4: W = Wn2; break;
            default: W = Ws2; break;
        }
        float v = W[k * 128 + n];
        __nv_bfloat16 h = __float2bfloat16(v);
        __nv_bfloat16 l = __float2bfloat16(v - __bfloat162float(h));
        wh[mat * 16384 + n * 128 + k] = h;
        wl[mat * 16384 + n * 128 + k] = l;
    } else {
        int zb = b - PREP_WS_B;
        int i = zb * 256 + t;
        if (i < N_NODES) g_deg[i] = 0;
        if (zb == 0) {
            if (t < NCHUNK) g_bsum[t] = -1;
            if (t == NCHUNK)     g_done1 = 0;
            if (t == NCHUNK + 1) g_done2 = 0;
        }
    }
}

// ---------------- fused hist + scan + fill (NCHUNK x 1024 co-resident) ----------------
__global__ void __launch_bounds__(SCAN_B)
k_scanfill(const int* __restrict__ src, const int* __restrict__ dst) {
    __shared__ int s[SCAN_B];
    __shared__ int agg_sh[NCHUNK];
    __shared__ int s_off;
    const int bid = blockIdx.x;
    const int tid = threadIdx.x;
    const int gi = bid * SCAN_B + tid;

    // ---- phase 0: histogram ----
    for (int e = bid * SCAN_B + tid; e < N_EDGES; e += NCHUNK * SCAN_B) {
        atomicAdd(&g_deg[dst[e]], 1);
    }
    __threadfence();
    __syncthreads();
    if (tid == 0) {
        atomicAdd((int*)&g_done1, 1);
        while (g_done1 < NCHUNK) { }
    }
    __syncthreads();

    // ---- phase 1: scan ----
    int v = (gi < N_NODES) ? g_deg[gi] : 0;
    s[tid] = v;
    __syncthreads();
#pragma unroll
    for (int off = 1; off < SCAN_B; off <<= 1) {
        int t = (tid >= off) ? s[tid - off] : 0;
        __syncthreads();
        s[tid] += t;
        __syncthreads();
    }
    int inclusive = s[tid];
    int local_ex = inclusive - v;

    if (tid == SCAN_B - 1) {
        __threadfence();
        g_bsum[bid] = inclusive;   // publish chunk aggregate
    }
    if (tid < NCHUNK) {
        int val = 0;
        if (tid < bid) {
            do { val = g_bsum[tid]; } while (val < 0);
        }
        agg_sh[tid] = (tid < bid) ? val : 0;
    }
    __syncthreads();
    if (tid == 0) {
        int run = 0;
#pragma unroll 1
        for (int i = 0; i < NCHUNK; i++) run += agg_sh[i];
        s_off = run;
    }
    __syncthreads();
    int offset = s_off;

    if (gi < N_NODES) {
        int p = local_ex + offset;
        g_csr_ptr[gi] = p;
        g_cursor[gi]  = p;
        g_deg_inv[gi] = 1.0f / (float)max(v, 1);
    }
    if (gi == 0) g_csr_ptr[N_NODES] = N_EDGES;

    // ---- barrier ----
    __threadfence();
    __syncthreads();
    if (tid == 0) {
        atomicAdd((int*)&g_done2, 1);
        while (g_done2 < NCHUNK) { }
    }
    __syncthreads();

    // ---- phase 2: fill ----
    for (int e = bid * SCAN_B + tid; e < N_EDGES; e += NCHUNK * SCAN_B) {
        int pos = atomicAdd(&g_cursor[dst[e]], 1);
        g_csr_src[pos] = src[e];
    }
}

// ---------------- fp32 mean aggregation: one warp per node, 4-deep batches ----------------
__global__ void k_aggregate(const float* __restrict__ in, float* __restrict__ out) {
    int warp = (blockIdx.x * blockDim.x + threadIdx.x) >> 5;
    int lane = threadIdx.x & 31;
    if (warp >= N_NODES) return;
    int beg = g_csr_ptr[warp];
    int end = g_csr_ptr[warp + 1];

    float4 acc[4];
#pragma unroll
    for (int u = 0; u < 4; ++u) acc[u] = make_float4(0.f, 0.f, 0.f, 0.f);

    int e = beg;
#pragma unroll 1
    for (; e + 4 <= end; e += 4) {
        int s[4];
#pragma unroll
        for (int u = 0; u < 4; ++u) s[u] = g_csr_src[e + u];
        float4 r[4];
#pragma unroll
        for (int u = 0; u < 4; ++u)
            r[u] = __ldg(((const float4*)(in + (size_t)s[u] * D)) + lane);
#pragma unroll
        for (int u = 0; u < 4; ++u) {
            acc[u].x += r[u].x; acc[u].y += r[u].y;
            acc[u].z += r[u].z; acc[u].w += r[u].w;
        }
    }
#pragma unroll 1
    for (; e < end; ++e) {
        int s = g_csr_src[e];
        float4 r = __ldg(((const float4*)(in + (size_t)s * D)) + lane);
        acc[0].x += r.x; acc[0].y += r.y; acc[0].z += r.z; acc[0].w += r.w;
    }
    float4 o;
    o.x = acc[0].x + acc[1].x + acc[2].x + acc[3].x;
    o.y = acc[0].y + acc[1].y + acc[2].y + acc[3].y;
    o.z = acc[0].z + acc[1].z + acc[2].z + acc[3].z;
    o.w = acc[0].w + acc[1].w + acc[2].w + acc[3].w;
    float di = g_deg_inv[warp];
    o.x *= di; o.y *= di; o.z *= di; o.w *= di;
    ((float4*)(out + (size_t)warp * D))[lane] = o;
}

// ---------------- mma.sync fused SAGE GEMM (2 CTAs/SM) ----------------
#define TSTRIDE 144
#define TILE_BYTES (128 * TSTRIDE)
#define SM_BIAS  256
#define SM_AHI   1024
#define SM_ALO   (SM_AHI + TILE_BYTES)
#define SM_BHI   (SM_ALO + TILE_BYTES)
#define SM_BLO   (SM_BHI + TILE_BYTES)
#define SM_NEED  (SM_BLO + TILE_BYTES + 1024)

__global__ void __launch_bounds__(256, 2)
k_sage_mma(const float* __restrict__ Xs, const float* __restrict__ Mn,
           const __nv_bfloat16* __restrict__ wh, const __nv_bfloat16* __restrict__ wl,
           const float* __restrict__ bias, float* __restrict__ out, int relu) {
    extern __shared__ __align__(16) char smraw[];
    uint32_t raw = smem_u32(smraw);
    uint32_t sbase = (raw + 1023u) & ~1023u;
    char* smem = smraw + (sbase - raw);

    const int tid = threadIdx.x;
    const int wid = tid >> 5;
    const int lid = tid & 31;
    const int block_row = blockIdx.x * 128;
    const int mrow = (wid & 3) * 32;
    const int ncol = (wid >> 2) * 64;

    float* sbias = (float*)(smem + SM_BIAS);
    if (tid < 128) sbias[tid] = bias[tid];

    float acc[2][8][4];
#pragma unroll
    for (int mb = 0; mb < 2; ++mb)
#pragma unroll
        for (int nb = 0; nb < 8; ++nb)
#pragma unroll
            for (int r = 0; r < 4; ++r) acc[mb][nb][r] = 0.f;

    const uint32_t a_lane_off = (uint32_t)(((lid & 7) + ((lid >> 3) & 1) * 8) * TSTRIDE
                                           + ((lid >> 4) * 8) * 2);
    const uint32_t b_lane_off = (uint32_t)((((lid >> 4) * 8) + (lid & 7)) * TSTRIDE
                                           + (((lid >> 3) & 1) * 8) * 2);

#pragma unroll 1
    for (int c = 0; c < 4; ++c) {
        const int phase = c >> 1;
        const int kc = c & 1;
        const float* __restrict__ A = phase ? Xs : Mn;
        const __nv_bfloat16* __restrict__ bhsrc = wh + phase * 16384 + kc * 64;
        const __nv_bfloat16* __restrict__ blsrc = wl + phase * 16384 + kc * 64;

        __syncthreads();

#pragma unroll
        for (int it = 0; it < 4; ++it) {
            int g = tid + it * 256;
            int row = g >> 3, seg = g & 7;
            int grow = block_row + row;
            float4 v0 = make_float4(0.f, 0.f, 0.f, 0.f), v1 = v0;
            if (grow < N_NODES) {
                const float4* p = (const float4*)(A + (size_t)grow * D + kc * 64 + seg * 8);
                v0 = p[0]; v1 = p[1];
            }
            float f[8] = {v0.x, v0.y, v0.z, v0.w, v1.x, v1.y, v1.z, v1.w};
            uint32_t hv[4], lv[4];
#pragma unroll
            for (int eI = 0; eI < 4; ++eI) {
                float a0 = f[2 * eI], a1 = f[2 * eI + 1];
                __nv_bfloat16 h0 = __float2bfloat16(a0);
                __nv_bfloat16 h1 = __float2bfloat16(a1);
                __nv_bfloat16 l0 = __float2bfloat16(a0 - __bfloat162float(h0));
                __nv_bfloat16 l1 = __float2bfloat16(a1 - __bfloat162float(h1));
                hv[eI] = (uint32_t)__bfloat16_as_ushort(h0) |
                         ((uint32_t)__bfloat16_as_ushort(h1) << 16);
                lv[eI] = (uint32_t)__bfloat16_as_ushort(l0) |
                         ((uint32_t)__bfloat16_as_ushort(l1) << 16);
            }
            uint32_t off = (uint32_t)(row * TSTRIDE + seg * 16);
            *(uint4*)(smem + SM_AHI + off) = make_uint4(hv[0], hv[1], hv[2], hv[3]);
            *(uint4*)(smem + SM_ALO + off) = make_uint4(lv[0], lv[1], lv[2], lv[3]);
        }
#pragma unroll
        for (int it = 0; it < 4; ++it) {
            int g = tid + it * 256;
            int n = g >> 3, seg = g & 7;
            uint32_t off = (uint32_t)(n * TSTRIDE + seg * 16);
            *(uint4*)(smem + SM_BHI + off) = *(const uint4*)(bhsrc + n * 128 + seg * 8);
            *(uint4*)(smem + SM_BLO + off) = *(const uint4*)(blsrc + n * 128 + seg * 8);
        }
        __syncthreads();

        const uint32_t ahi_base = sbase + SM_AHI + (uint32_t)(mrow * TSTRIDE) + a_lane_off;
        const uint32_t alo_base = sbase + SM_ALO + (uint32_t)(mrow * TSTRIDE) + a_lane_off;
        const uint32_t bhi_base = sbase + SM_BHI + (uint32_t)(ncol * TSTRIDE) + b_lane_off;
        const uint32_t blo_base = sbase + SM_BLO + (uint32_t)(ncol * TSTRIDE) + b_lane_off;

#pragma unroll
        for (int k16 = 0; k16 < 4; ++k16) {
            const uint32_t kb = (uint32_t)(k16 * 32);
            uint32_t ah[2][4], al[2][4];
#pragma unroll
            for (int mb = 0; mb < 2; ++mb) {
                uint32_t mo = (uint32_t)(mb * 16 * TSTRIDE) + kb;
                ldm_x4(ah[mb][0], ah[mb][1], ah[mb][2], ah[mb][3], ahi_base + mo);
                ldm_x4(al[mb][0], al[mb][1], al[mb][2], al[mb][3], alo_base + mo);
            }
#pragma unroll
            for (int jp = 0; jp < 4; ++jp) {
                uint32_t no = (uint32_t)(jp * 16 * TSTRIDE) + kb;
                uint32_t bh[4], bl[4];
                ldm_x4(bh[0], bh[1], bh[2], bh[3], bhi_base + no);
                ldm_x4(bl[0], bl[1], bl[2], bl[3], blo_base + no);
#pragma unroll
                for (int mb = 0; mb < 2; ++mb) {
                    mma_bf16(acc[mb][jp * 2 + 0], ah[mb], bh + 0);
                    mma_bf16(acc[mb][jp * 2 + 1], ah[mb], bh + 2);
                    mma_bf16(acc[mb][jp * 2 + 0], ah[mb], bl + 0);
                    mma_bf16(acc[mb][jp * 2 + 1], ah[mb], bl + 2);
                    mma_bf16(acc[mb][jp * 2 + 0], al[mb], bh + 0);
                    mma_bf16(acc[mb][jp * 2 + 1], al[mb], bh + 2);
                }
            }
        }
    }

    // ---- epilogue ----
    const int r4 = lid >> 2;
    const int c2 = (lid & 3) * 2;
#pragma unroll
    for (int mb = 0; mb < 2; ++mb) {
#pragma unroll
        for (int nb = 0; nb < 8; ++nb) {
            int col = ncol + nb * 8 + c2;
            float b0 = sbias[col], b1 = sbias[col + 1];
            int row0 = block_row + mrow + mb * 16 + r4;
            int row1 = row0 + 8;
            float2 o0, o1;
            o0.x = acc[mb][nb][0] + b0; o0.y = acc[mb][nb][1] + b1;
            o1.x = acc[mb][nb][2] + b0; o1.y = acc[mb][nb][3] + b1;
            if (relu) {
                o0.x = fmaxf(o0.x, 0.f); o0.y = fmaxf(o0.y, 0.f);
                o1.x = fmaxf(o1.x, 0.f); o1.y = fmaxf(o1.y, 0.f);
            }
            if (row0 < N_NODES) *(float2*)(out + (size_t)row0 * D + col) = o0;
            if (row1 < N_NODES) *(float2*)(out + (size_t)row1 * D + col) = o1;
        }
    }
}

// ---------------- final fc (128->16) + log_softmax, one warp per node ----------------
__global__ void k_fc_logsoftmax(const float* __restrict__ emb,
                                const float* __restrict__ Wfc,
                                const float* __restrict__ bfc,
                                float* __restrict__ outp) {
    __shared__ float sWt[D_OUT * D];
    __shared__ float sb[D_OUT];
    for (int i = threadIdx.x; i < D * D_OUT; i += blockDim.x) {
        int k = i >> 4, j = i & 15;
        sWt[j * D + k] = Wfc[i];
    }
    if (threadIdx.x < D_OUT) sb[threadIdx.x] = bfc[threadIdx.x];
    __syncthreads();

    int warp = (blockIdx.x * blockDim.x + threadIdx.x) >> 5;
    int lane = threadIdx.x & 31;
    if (warp >= N_NODES) return;

    float4 e4 = ((const float4*)(emb + (size_t)warp * D))[lane];
    float y[D_OUT];
#pragma unroll
    for (int j = 0; j < D_OUT; j++) {
        float4 w = ((const float4*)(sWt + j * D))[lane];
        y[j] = e4.x * w.x + e4.y * w.y + e4.z * w.z + e4.w * w.w;
    }
#pragma unroll
    for (int off = 16; off >= 1; off >>= 1)
#pragma unroll
        for (int j = 0; j < D_OUT; j++)
            y[j] += __shfl_xor_sync(0xFFFFFFFFu, y[j], off);

    float m = -1e30f;
#pragma unroll
    for (int j = 0; j < D_OUT; j++) { y[j] += sb[j]; m = fmaxf(m, y[j]); }
    float ssum = 0.f;
#pragma unroll
    for (int j = 0; j < D_OUT; j++) ssum += __expf(y[j] - m);
    float lse = __logf(ssum) + m;
    if (lane < D_OUT) outp[(size_t)warp * D_OUT + lane] = y[lane] - lse;
}

// ---------------- launcher ----------------
extern "C" void kernel_launch(void* const* d_in, const int* in_sizes, int n_in,
                              void* d_out, int out_size) {
    const float* x   = (const float*)d_in[0];
    const int*   ei  = (const int*)d_in[1];
    const float* Wn0 = (const float*)d_in[2];
    const float* Ws0 = (const float*)d_in[3];
    const float* b0  = (const float*)d_in[4];
    const float* Wn1 = (const float*)d_in[5];
    const float* Ws1 = (const float*)d_in[6];
    const float* b1  = (const float*)d_in[7];
    const float* Wn2 = (const float*)d_in[8];
    const float* Ws2 = (const float*)d_in[9];
    const float* b2  = (const float*)d_in[10];
    const float* Wfc = (const float*)d_in[11];
    const float* bfc = (const float*)d_in[12];

    float* out  = (float*)d_out;
    float* emb  = out;                               // [N, 128]
    float* logp = out + (size_t)N_NODES * D;         // [N, 16]

    const int* src = ei;
    const int* dst = ei + N_EDGES;

    void *p_mean, *p_A, *p_B, *p_wh, *p_wl;
    cudaGetSymbolAddress(&p_mean, g_mean);
    cudaGetSymbolAddress(&p_A, g_bufA);
    cudaGetSymbolAddress(&p_B, g_bufB);
    cudaGetSymbolAddress(&p_wh, g_wh);
    cudaGetSymbolAddress(&p_wl, g_wl);
    float* mean = (float*)p_mean;
    float* A = (float*)p_A;
    float* B = (float*)p_B;
    __nv_bfloat16* wh = (__nv_bfloat16*)p_wh;
    __nv_bfloat16* wl = (__nv_bfloat16*)p_wl;

    static int smem_set = 0;
    if (!smem_set) {
        cudaFuncSetAttribute(k_sage_mma, cudaFuncAttributeMaxDynamicSharedMemorySize, SM_NEED);
        smem_set = 1;
    }

    const int GEMM_B = (N_NODES + 127) / 128;      // 782
    const int WARP_B = (N_NODES * 32 + 255) / 256; // 12500

    // 1: prep
    k_prep<<<PREP_GRID, 256>>>(Wn0, Ws0, Wn1, Ws1, Wn2, Ws2, wh, wl);
    // 2: fused hist + scan + fill
    k_scanfill<<<NCHUNK, SCAN_B>>>(src, dst);

    // 3: layer-0 aggregate
    k_aggregate<<<WARP_B, 256>>>(x, mean);
    // 4: layer-0 gemm  <-- profiled launch
    k_sage_mma<<<GEMM_B, 256, SM_NEED>>>(x, mean, wh + 0 * 16384, wl + 0 * 16384, b0, A, 1);
    // layer 1
    k_aggregate<<<WARP_B, 256>>>(A, mean);
    k_sage_mma<<<GEMM_B, 256, SM_NEED>>>(A, mean, wh + 2 * 16384, wl + 2 * 16384, b1, B, 1);
    // layer 2 -> emb into d_out
    k_aggregate<<<WARP_B, 256>>>(B, mean);
    k_sage_mma<<<GEMM_B, 256, SM_NEED>>>(B, mean, wh + 4 * 16384, wl + 4 * 16384, b2, emb, 0);
    // fc + log_softmax
    k_fc_logsoftmax<<<WARP_B, 256>>>(emb, Wfc, bfc, logp);
}